// round 2
// baseline (speedup 1.0000x reference)
#include <cuda_runtime.h>

#define CC      32
#define TT      256
#define HALO    63
#define EXT     319          // TT + HALO
#define NTHR    320
#define LLEN    90000
#define NTILES  352          // ceil(90000/256)
#define NB      8
#define DOWNL   22500
#define FLATN   (64*DOWNL)   // 1,440,000
#define SLICE   3200
#define NSLICE  450          // 1,440,000 / 3200

// scratch (static device globals: no runtime allocation)
__device__ float g_y[NB * FLATN];             // downsampled feature map [8][64][22500]
__device__ float g_partial[NSLICE * 64 * NB]; // FC partial sums

// ---------------------------------------------------------------------------
// Kernel 1: fused initial conv + 6 wavenet blocks + stride-4 downsample conv.
// One CTA = one (batch, 256-position tile). h lives entirely in shared memory
// (left halo of 63 covers the cumulative receptive field of all dilations).
// ---------------------------------------------------------------------------
__global__ __launch_bounds__(NTHR, 1)
void k_wavenet(const float* __restrict__ x,
               const float* __restrict__ w0, const float* __restrict__ b0,
               const float* __restrict__ Wf, const float* __restrict__ bf,
               const float* __restrict__ Wg, const float* __restrict__ bg,
               const float* __restrict__ Ws, const float* __restrict__ bs,
               const float* __restrict__ Wr, const float* __restrict__ br,
               const float* __restrict__ wd, const float* __restrict__ bd)
{
    extern __shared__ float sm[];
    float* hs    = sm;                    // [CC][NTHR]  h tile (in-place updated)
    float* wbuf  = hs + CC*NTHR;          // 8192 floats: wfg[1024 float4] | wsrT[2048]
    float* skipb = wbuf + 8192;           // [CC][TT]    skip staging for downsample
    float* bbuf  = skipb + CC*TT;         // 128 floats: bf|bg|bs|br of current block
    float* xs    = bbuf + 128;            // EXT+2 input samples

    const int b    = blockIdx.y;
    const int tile = blockIdx.x;
    const int l0   = tile * TT;
    const int t    = threadIdx.x;
    const int p    = l0 - HALO + t;       // owned sequence position (t < EXT)

    // ---- load x tile (with 65-left halo: 63 for blocks + 2 for K=3 conv) ----
    for (int i = t; i < EXT + 2; i += NTHR) {
        int gp = l0 - HALO - 2 + i;
        xs[i] = (gp >= 0 && gp < LLEN) ? x[(size_t)b*LLEN + gp] : 0.f;
    }
    __syncthreads();

    // ---- initial causal conv K=3: h[c][t] ----
    if (t < EXT) {
        if (p >= 0 && p < LLEN) {
            float x0 = xs[t], x1 = xs[t+1], x2 = xs[t+2];
            #pragma unroll
            for (int c = 0; c < CC; c++) {
                hs[c*NTHR + t] = __ldg(&b0[c]) + __ldg(&w0[c*3+0])*x0
                               + __ldg(&w0[c*3+1])*x1 + __ldg(&w0[c*3+2])*x2;
            }
        } else {
            #pragma unroll
            for (int c = 0; c < CC; c++) hs[c*NTHR + t] = 0.f;  // causal zero-pad
        }
    }

    float skip[CC];
    #pragma unroll
    for (int c = 0; c < CC; c++) skip[c] = 0.f;
    const bool doskip = (t >= HALO) && (t < EXT) && (p < LLEN);

    // ---- 6 dilated residual blocks ----
    for (int blk = 0; blk < 6; blk++) {
        const int d = 1 << blk;

        // stage weights: wfg[o][c] = (Wf0,Wf1,Wg0,Wg1); wsrT[o][oo] = (Ws[oo][o], Wr[oo][o])
        for (int idx = t; idx < 1024; idx += NTHR) {
            float4 v;
            v.x = Wf[(blk*1024 + idx)*2 + 0];
            v.y = Wf[(blk*1024 + idx)*2 + 1];
            v.z = Wg[(blk*1024 + idx)*2 + 0];
            v.w = Wg[(blk*1024 + idx)*2 + 1];
            ((float4*)wbuf)[idx] = v;
            int oo = idx >> 5, o = idx & 31;          // global layout Ws[oo][o]
            float2 u;
            u.x = Ws[blk*1024 + idx];
            u.y = Wr[blk*1024 + idx];
            ((float2*)(wbuf + 4096))[o*CC + oo] = u;  // transposed for inner loop
        }
        if (t < 32) {
            bbuf[t]      = bf[blk*CC + t];
            bbuf[32 + t] = bg[blk*CC + t];
            bbuf[64 + t] = bs[blk*CC + t];
            bbuf[96 + t] = br[blk*CC + t];
        }
        __syncthreads();

        const int S = (2 << blk) - 1;   // first valid column for this block
        const bool act = (t >= S) && (t < EXT) && (p >= 0) && (p < LLEN);
        float racc[CC];

        if (act) {
            float hc[CC], hp[CC];
            #pragma unroll
            for (int c = 0; c < CC; c++) {
                hc[c] = hs[c*NTHR + t];
                hp[c] = hs[c*NTHR + t - d];
            }
            #pragma unroll
            for (int c = 0; c < CC; c++) racc[c] = bbuf[96 + c];
            if (doskip) {
                #pragma unroll
                for (int c = 0; c < CC; c++) skip[c] += bbuf[64 + c];
            }

            #pragma unroll 1
            for (int o = 0; o < CC; o++) {
                float af0 = bbuf[o],      af1 = 0.f;
                float ag0 = bbuf[32 + o], ag1 = 0.f;
                const float4* wp = ((const float4*)wbuf) + o*CC;
                #pragma unroll
                for (int c = 0; c < CC; c += 2) {
                    float4 wa = wp[c];
                    af0 = fmaf(wa.x, hp[c],   af0); af0 = fmaf(wa.y, hc[c],   af0);
                    ag0 = fmaf(wa.z, hp[c],   ag0); ag0 = fmaf(wa.w, hc[c],   ag0);
                    float4 wb = wp[c+1];
                    af1 = fmaf(wb.x, hp[c+1], af1); af1 = fmaf(wb.y, hc[c+1], af1);
                    ag1 = fmaf(wb.z, hp[c+1], ag1); ag1 = fmaf(wb.w, hc[c+1], ag1);
                }
                float af = af0 + af1, ag = ag0 + ag1;
                // tanh via exp (overflow-safe), sigmoid via exp; rel err ~1e-6
                float e2 = __expf(-2.f * fabsf(af));
                float th = copysignf(__fdividef(1.f - e2, 1.f + e2), af);
                float sg = __fdividef(1.f, 1.f + __expf(-ag));
                float out_o = th * sg;

                const float4* wsp = ((const float4*)(wbuf + 4096)) + o*(CC/2);
                if (doskip) {
                    #pragma unroll
                    for (int oo = 0; oo < CC; oo += 2) {
                        float4 w = wsp[oo >> 1];
                        skip[oo]   = fmaf(w.x, out_o, skip[oo]);
                        racc[oo]   = fmaf(w.y, out_o, racc[oo]);
                        skip[oo+1] = fmaf(w.z, out_o, skip[oo+1]);
                        racc[oo+1] = fmaf(w.w, out_o, racc[oo+1]);
                    }
                } else {
                    #pragma unroll
                    for (int oo = 0; oo < CC; oo += 2) {
                        float4 w = wsp[oo >> 1];
                        racc[oo]   = fmaf(w.y, out_o, racc[oo]);
                        racc[oo+1] = fmaf(w.w, out_o, racc[oo+1]);
                    }
                }
            }
        }
        __syncthreads();                       // all hs reads done
        if (act) {
            #pragma unroll
            for (int c = 0; c < CC; c++) hs[c*NTHR + t] += racc[c];   // h += r
        }
        __syncthreads();                       // hs updated for next block
    }

    // ---- stage skip to smem ----
    if (t >= HALO && t < EXT) {
        int j = t - HALO;
        #pragma unroll
        for (int c = 0; c < CC; c++) skipb[c*TT + j] = (p < LLEN) ? skip[c] : 0.f;
    }
    __syncthreads();

    // ---- downsample conv: 64 out-ch, K=4, stride 4 (reuse wbuf for wd) ----
    for (int idx = t; idx < 2048; idx += NTHR)
        ((float4*)wbuf)[idx] = ((const float4*)wd)[idx];   // 64*32*4 = 8192 floats
    __syncthreads();

    const int m0 = tile * (TT/4);
    for (int idx = t; idx < 64*64; idx += NTHR) {
        int m = idx & 63, o = idx >> 6;
        int mg = m0 + m;
        if (mg < DOWNL) {
            float acc = __ldg(&bd[o]);
            #pragma unroll
            for (int c = 0; c < CC; c++) {
                float4 w  = ((const float4*)wbuf)[o*CC + c];
                float4 s4 = ((const float4*)skipb)[c*(TT/4) + m];
                acc += w.x*s4.x + w.y*s4.y + w.z*s4.z + w.w*s4.w;
            }
            g_y[(size_t)b*FLATN + (size_t)o*DOWNL + mg] = acc;
        }
    }
}

// ---------------------------------------------------------------------------
// Kernel 2: FC partials. One CTA per 3200-element f-slice; y slice cached in
// smem, each warp handles 8 fcW rows (as 4 pairs sharing y loads).
// ---------------------------------------------------------------------------
__global__ __launch_bounds__(256)
void k_fc(const float* __restrict__ fcW)
{
    extern __shared__ float ys[];   // [NB][SLICE]
    const int t = threadIdx.x;
    const int slice = blockIdx.x;
    const size_t f0 = (size_t)slice * SLICE;

    for (int idx = t; idx < NB*(SLICE/4); idx += 256) {
        int bb = idx / (SLICE/4);
        int q  = idx % (SLICE/4);
        ((float4*)ys)[idx] = ((const float4*)(g_y + (size_t)bb*FLATN + f0))[q];
    }
    __syncthreads();

    const int warp = t >> 5, lane = t & 31;
    #pragma unroll 1
    for (int jp = 0; jp < 4; jp++) {
        int j0 = warp*8 + jp*2;
        const float4* w0p = (const float4*)(fcW + (size_t)j0*FLATN + f0);
        const float4* w1p = (const float4*)(fcW + (size_t)(j0+1)*FLATN + f0);
        float a0[NB], a1[NB];
        #pragma unroll
        for (int bb = 0; bb < NB; bb++) { a0[bb] = 0.f; a1[bb] = 0.f; }

        for (int q = lane; q < SLICE/4; q += 32) {
            float4 w0v = __ldg(w0p + q);
            float4 w1v = __ldg(w1p + q);
            #pragma unroll
            for (int bb = 0; bb < NB; bb++) {
                float4 yv = ((const float4*)ys)[bb*(SLICE/4) + q];
                a0[bb] += w0v.x*yv.x + w0v.y*yv.y + w0v.z*yv.z + w0v.w*yv.w;
                a1[bb] += w1v.x*yv.x + w1v.y*yv.y + w1v.z*yv.z + w1v.w*yv.w;
            }
        }
        #pragma unroll
        for (int bb = 0; bb < NB; bb++) {
            #pragma unroll
            for (int off = 16; off > 0; off >>= 1) {
                a0[bb] += __shfl_xor_sync(0xffffffffu, a0[bb], off);
                a1[bb] += __shfl_xor_sync(0xffffffffu, a1[bb], off);
            }
        }
        if (lane == 0) {
            #pragma unroll
            for (int bb = 0; bb < NB; bb++) {
                g_partial[((size_t)slice*64 + j0  )*NB + bb] = a0[bb];
                g_partial[((size_t)slice*64 + j0+1)*NB + bb] = a1[bb];
            }
        }
    }
}

// ---------------------------------------------------------------------------
// Kernel 3: reduce FC partials, add bias, reparameterize, write (mu,logvar,z)
// ---------------------------------------------------------------------------
__global__ void k_final(const float* __restrict__ fcb,
                        const float* __restrict__ eps,
                        float* __restrict__ out)
{
    __shared__ float os[64][NB];
    const int t = threadIdx.x;           // 512 threads
    const int j = t >> 3, bb = t & 7;
    float acc = fcb[j];
    for (int s = 0; s < NSLICE; s++)
        acc += g_partial[(size_t)s*64*NB + t];   // (s*64+j)*8+bb == s*512+t
    os[j][bb] = acc;
    __syncthreads();
    if (t < 256) {
        int b2 = t >> 5, c = t & 31;
        float mu = os[c][b2];
        float lv = os[c + 32][b2];
        float z  = mu + eps[b2*32 + c] * expf(0.5f * lv);
        out[        b2*32 + c] = mu;
        out[256  +  b2*32 + c] = lv;
        out[512  +  b2*32 + c] = z;
    }
}

// ---------------------------------------------------------------------------
extern "C" void kernel_launch(void* const* d_in, const int* in_sizes, int n_in,
                              void* d_out, int out_size)
{
    const float* x   = (const float*)d_in[0];
    const float* eps = (const float*)d_in[1];
    const float* w0  = (const float*)d_in[2];
    const float* b0  = (const float*)d_in[3];
    const float* Wf  = (const float*)d_in[4];
    const float* bf  = (const float*)d_in[5];
    const float* Wg  = (const float*)d_in[6];
    const float* bg  = (const float*)d_in[7];
    const float* Ws  = (const float*)d_in[8];
    const float* bs  = (const float*)d_in[9];
    const float* Wr  = (const float*)d_in[10];
    const float* br  = (const float*)d_in[11];
    const float* wd  = (const float*)d_in[12];
    const float* bd  = (const float*)d_in[13];
    const float* fcW = (const float*)d_in[14];
    const float* fcb = (const float*)d_in[15];
    float* out = (float*)d_out;

    const int smem1 = (CC*NTHR + 8192 + CC*TT + 128 + EXT + 2) * (int)sizeof(float);
    const int smem2 = NB * SLICE * (int)sizeof(float);
    cudaFuncSetAttribute(k_wavenet, cudaFuncAttributeMaxDynamicSharedMemorySize, smem1);
    cudaFuncSetAttribute(k_fc,      cudaFuncAttributeMaxDynamicSharedMemorySize, smem2);

    dim3 g1(NTILES, NB);
    k_wavenet<<<g1, NTHR, smem1>>>(x, w0, b0, Wf, bf, Wg, bg, Ws, bs, Wr, br, wd, bd);
    k_fc<<<NSLICE, 256, smem2>>>(fcW);
    k_final<<<1, 512>>>(fcb, eps, out);
}